// round 5
// baseline (speedup 1.0000x reference)
#include <cuda_runtime.h>
#include <cuda_bf16.h>

// ---------------------------------------------------------------------------
// Problem shape (fixed): B=4 batches, M=256 bins, N = in_sizes[0]/B particles.
// joint[b,i,j] = sum_n exp(-0.5((x[b,n]-bins[i])/h)^2) * exp(-0.5((y[b,n]-bins[j])/h)^2)
// out = joint / (sum_ij joint + 1e-10), h = bins[1]-bins[0].
// ---------------------------------------------------------------------------

#define NBATCH 4
#define MDIM   256
#define TILE   16
#define BUF    256   // smem particle staging slots (>= one full 256-thread chunk)
#define CPAD   20    // 16 table entries + 4 pad floats (keeps float4 alignment,
                     // staggers rows across smem banks)

// Scratch (static device arrays — no runtime allocation).
__device__ float g_joint[NBATCH * MDIM * MDIM];
__device__ float g_sum[NBATCH];

// Single-MUFU base-2 exponential; flushes to +0 for large negative args,
// matching fp32 expf's effective support. Rel err ~2^-22.
__device__ __forceinline__ float ex2f(float a) {
    float r;
    asm("ex2.approx.ftz.f32 %0, %1;" : "=f"(r) : "f"(a));
    return r;
}

// Process the staged particle buffer:
//   phase A: build kx/ky tables (c particles x 16 bins each axis) in smem
//   phase B: every thread accumulates its private 4x4 sub-block over its
//            replica's particle subset (p == rrep mod 16).
// Deterministic: fixed iteration order, no atomics.
__device__ __forceinline__ void process_buf(
    int c,
    const float* px, const float* py,
    const float* sbx, const float* sby,
    float* kxT, float* kyT,
    float cexp, int tid, int rrep, int bi4, int bj4, float* acc)
{
    __syncthreads();   // staged px/py writes -> visible
    for (int t = tid; t < c * TILE; t += 256) {
        int p = t >> 4, k = t & 15;
        float dx = px[p] - sbx[k];
        float dy = py[p] - sby[k];
        kxT[p * CPAD + k] = ex2f(cexp * dx * dx);
        kyT[p * CPAD + k] = ex2f(cexp * dy * dy);
    }
    __syncthreads();   // tables ready
    for (int p = rrep; p < c; p += 16) {
        float4 kx = *(const float4*)(kxT + p * CPAD + bi4);
        float4 ky = *(const float4*)(kyT + p * CPAD + bj4);
        acc[ 0] += kx.x * ky.x;  acc[ 1] += kx.x * ky.y;
        acc[ 2] += kx.x * ky.z;  acc[ 3] += kx.x * ky.w;
        acc[ 4] += kx.y * ky.x;  acc[ 5] += kx.y * ky.y;
        acc[ 6] += kx.y * ky.z;  acc[ 7] += kx.y * ky.w;
        acc[ 8] += kx.z * ky.x;  acc[ 9] += kx.z * ky.y;
        acc[10] += kx.z * ky.z;  acc[11] += kx.z * ky.w;
        acc[12] += kx.w * ky.x;  acc[13] += kx.w * ky.y;
        acc[14] += kx.w * ky.z;  acc[15] += kx.w * ky.w;
    }
    __syncthreads();   // buffer / tables may be reused after return
}

// One CTA per 16x16 output tile per batch. grid = (16, 16, 4), 256 threads.
__global__ void __launch_bounds__(256, 4)
tile_kernel(const float* __restrict__ x, const float* __restrict__ y,
            const float* __restrict__ bins, int N)
{
    __shared__ float sbx[TILE], sby[TILE];
    __shared__ float px[BUF], py[BUF];
    __shared__ float kxT[BUF * CPAD];
    __shared__ float kyT[BUF * CPAD];
    __shared__ int   sWarpCnt[8];

    const int tid = threadIdx.x;
    const int i0  = blockIdx.x * TILE;   // x-bin (row) tile origin
    const int j0  = blockIdx.y * TILE;   // y-bin (col) tile origin
    const int b   = blockIdx.z;

    if (tid < TILE)            sbx[tid]        = bins[i0 + tid];
    else if (tid < 2 * TILE)   sby[tid - TILE] = bins[j0 + (tid - TILE)];
    __syncthreads();

    const float h    = bins[1] - bins[0];
    // exp(-0.5 (d/h)^2) == 0 in fp32 (incl. denormals) once |d|/h > 14.4;
    // 14.6 gives margin, so dropped particles contribute exactly 0 in the
    // reference too -> no approximation.
    const float cut  = 14.6f * h;
    const float cexp = -0.72134752044f / (h * h);   // -0.5*log2(e)/h^2
    const float lox = sbx[0] - cut, hix = sbx[TILE - 1] + cut;
    const float loy = sby[0] - cut, hiy = sby[TILE - 1] + cut;

    // 16 replicas x 16 threads; each thread owns a 4x4 sub-block.
    const int sub  = tid & 15;
    const int rrep = tid >> 4;
    const int bi4  = (sub & 3) * 4;   // row offset within tile
    const int bj4  = (sub >> 2) * 4;  // col offset within tile

    float acc[16];
#pragma unroll
    for (int q = 0; q < 16; q++) acc[q] = 0.f;

    const float* __restrict__ xb = x + b * N;
    const float* __restrict__ yb = y + b * N;

    int bufCount = 0;
    for (int base = 0; base < N; base += 256) {
        const int idx = base + tid;
        float xv = 0.f, yv = 0.f;
        bool ok = false;
        if (idx < N) {
            xv = __ldg(xb + idx);
            yv = __ldg(yb + idx);
            ok = (xv >= lox) && (xv <= hix) && (yv >= loy) && (yv <= hiy);
        }
        const unsigned m = __ballot_sync(0xffffffffu, ok);
        if ((tid & 31) == 0) sWarpCnt[tid >> 5] = __popc(m);
        __syncthreads();

        const int myw = tid >> 5;
        int woff = 0, total = 0;
#pragma unroll
        for (int w = 0; w < 8; w++) {
            const int cw = sWarpCnt[w];
            woff  += (w < myw) ? cw : 0;
            total += cw;
        }
        // total/bufCount are uniform across the CTA -> flush branch is uniform.
        if (bufCount + total > BUF) {
            process_buf(bufCount, px, py, sbx, sby, kxT, kyT,
                        cexp, tid, rrep, bi4, bj4, acc);
            bufCount = 0;
        }
        if (ok) {
            const int pos = bufCount + woff +
                            __popc(m & ((1u << (tid & 31)) - 1u));
            px[pos] = xv;
            py[pos] = yv;
        }
        bufCount += total;
        __syncthreads();   // protect sWarpCnt reuse + staged writes
    }
    if (bufCount > 0)
        process_buf(bufCount, px, py, sbx, sby, kxT, kyT,
                    cexp, tid, rrep, bi4, bj4, acc);

    // Reduce the 16 replicas (fixed order -> deterministic). Reuse kxT.
    float* red = kxT;   // needs 16*256 floats = 16 KB < 20 KB available
#pragma unroll
    for (int q = 0; q < 16; q++)
        red[rrep * 256 + sub * 16 + q] = acc[q];
    __syncthreads();

    const int oi   = tid >> 4;            // tile-local output row
    const int oj   = tid & 15;            // tile-local output col
    const int sub2 = (oi >> 2) | ((oj >> 2) << 2);
    const int q2   = (oi & 3) * 4 + (oj & 3);
    float v = 0.f;
#pragma unroll
    for (int rr = 0; rr < 16; rr++)
        v += red[rr * 256 + sub2 * 16 + q2];

    g_joint[(b * MDIM + (i0 + oi)) * MDIM + (j0 + oj)] = v;
}

// Per-batch sum of the un-normalized joint (fixed-order tree reduction).
__global__ void sum_kernel()
{
    const int b = blockIdx.x;
    const float4* __restrict__ p =
        (const float4*)(g_joint + b * MDIM * MDIM);
    float s = 0.f;
    for (int t = threadIdx.x; t < (MDIM * MDIM) / 4; t += 256) {
        const float4 v = p[t];
        s += (v.x + v.y) + (v.z + v.w);
    }
    __shared__ float sm[256];
    sm[threadIdx.x] = s;
    __syncthreads();
    for (int off = 128; off > 0; off >>= 1) {
        if (threadIdx.x < off) sm[threadIdx.x] += sm[threadIdx.x + off];
        __syncthreads();
    }
    if (threadIdx.x == 0) g_sum[b] = sm[0] + 1e-10f;
}

// out = joint / sum  (float4 vectorized, one element per thread)
__global__ void norm_kernel(float* __restrict__ out, int n4)
{
    const int t = blockIdx.x * 256 + threadIdx.x;
    if (t >= n4) return;
    const int b = (t * 4) / (MDIM * MDIM);
    const float inv = 1.0f / g_sum[b];
    float4 v = ((const float4*)g_joint)[t];
    v.x *= inv; v.y *= inv; v.z *= inv; v.w *= inv;
    ((float4*)out)[t] = v;
}

extern "C" void kernel_launch(void* const* d_in, const int* in_sizes, int n_in,
                              void* d_out, int out_size)
{
    const float* x    = (const float*)d_in[0];   // (B, N) f32
    const float* y    = (const float*)d_in[1];   // (B, N) f32
    const float* bins = (const float*)d_in[2];   // (M,)  f32

    const int N = in_sizes[0] / NBATCH;

    dim3 grid(MDIM / TILE, MDIM / TILE, NBATCH);
    tile_kernel<<<grid, 256>>>(x, y, bins, N);

    sum_kernel<<<NBATCH, 256>>>();

    const int n4 = out_size / 4;   // out_size = B*M*M f32 elements
    norm_kernel<<<(n4 + 255) / 256, 256>>>((float*)d_out, n4);
}

// round 7
// speedup vs baseline: 1.5861x; 1.5861x over previous
#include <cuda_runtime.h>
#include <cuda_bf16.h>

// ---------------------------------------------------------------------------
// B=4 batches, M=256 bins, N = in_sizes[0]/B particles.
// joint[b,i,j] = sum_n exp(-0.5((x-bins[i])/h)^2) * exp(-0.5((y-bins[j])/h)^2)
// out = joint / (sum_ij joint + 1e-10), h = bins[1]-bins[0].
//
// exp term is EXACTLY 0 in fp32 once |d|/h > 14.4 (below denormal floor), so
// each particle touches <= ~29 bins/axis. We pre-bin particles into per-tile
// buckets (window cut = 14.6h, 0.2h slack >> fp rounding -> no approximation),
// then each 16x16-tile CTA processes only its bucket.
// ---------------------------------------------------------------------------

#define NBATCH 4
#define MDIM   256
#define TILE   16
#define NT     16      // tiles per axis (MDIM/TILE)
#define CAP    10240   // bucket capacity (max expected ~7.9k for central tile)
#define BUF    256     // particles staged per chunk
#define CPAD   20      // 16 table entries + 4 pad floats

// Static scratch (load-time allocation; no runtime alloc).
__device__ float2 g_bucket[NBATCH * NT * NT * CAP];   // ~84 MB, fits in L2+HBM
__device__ int    g_cnt[NBATCH * NT * NT];
__device__ float  g_joint[NBATCH * MDIM * MDIM];
__device__ float  g_sum[NBATCH];

__device__ __forceinline__ float ex2f(float a) {
    float r;
    asm("ex2.approx.ftz.f32 %0, %1;" : "=f"(r) : "f"(a));
    return r;
}

// ---------------------------------------------------------------------------
__global__ void zero_kernel()
{
    const int t = threadIdx.x;           // 1024 threads
    g_cnt[t] = 0;
    if (t < NBATCH) g_sum[t] = 0.f;
}

// ---------------------------------------------------------------------------
// One thread per particle: compute which tiles' windows contain it (<=3x3),
// scatter (x,y) into those buckets. Tile i window (bin units, t=(x-b0)/h):
//   16*i <= t + 14.6  &&  16*i + 15 >= t - 14.6
// -> i in [ceil((t-29.6)/16), floor((t+14.6)/16)].
__global__ void bin_kernel(const float* __restrict__ x,
                           const float* __restrict__ y,
                           const float* __restrict__ bins, int N)
{
    const int idx = blockIdx.x * 256 + threadIdx.x;
    const int b   = blockIdx.y;
    if (idx >= N) return;

    const float b0   = __ldg(bins);
    const float h    = __ldg(bins + 1) - b0;
    const float invh = 1.0f / h;

    const float xv = __ldg(x + b * N + idx);
    const float yv = __ldg(y + b * N + idx);
    const float tx = (xv - b0) * invh;
    const float ty = (yv - b0) * invh;

    const float s = 1.0f / 16.0f;
    const int ix0 = max(0,      (int)ceilf ((tx - 29.6f) * s));
    const int ix1 = min(NT - 1, (int)floorf((tx + 14.6f) * s));
    const int iy0 = max(0,      (int)ceilf ((ty - 29.6f) * s));
    const int iy1 = min(NT - 1, (int)floorf((ty + 14.6f) * s));

    const float2 v = make_float2(xv, yv);
    for (int i = ix0; i <= ix1; i++)
        for (int j = iy0; j <= iy1; j++) {
            const int id  = (b * NT + i) * NT + j;
            const int pos = atomicAdd(&g_cnt[id], 1);
            if (pos < CAP) g_bucket[id * CAP + pos] = v;
        }
}

// ---------------------------------------------------------------------------
// CTA (i,j,b) owns output tile rows [16i,16i+15] x cols [16j,16j+15].
// Per 256-particle chunk: stage -> build kx/ky tables (1 MUFU/value) ->
// 16-replica x (4x4 per-thread) outer-product accumulation -> tree-reduce.
__global__ void __launch_bounds__(256, 4)
tile_kernel(const float* __restrict__ bins)
{
    __shared__ float sbx[TILE], sby[TILE];
    __shared__ float px[BUF], py[BUF];
    __shared__ float kxT[BUF * CPAD];
    __shared__ float kyT[BUF * CPAD];

    const int tid = threadIdx.x;
    const int ti  = blockIdx.x;          // x-tile (output row block)
    const int tj  = blockIdx.y;          // y-tile (output col block)
    const int b   = blockIdx.z;
    const int i0  = ti * TILE;
    const int j0  = tj * TILE;

    if (tid < TILE)            sbx[tid]        = bins[i0 + tid];
    else if (tid < 2 * TILE)   sby[tid - TILE] = bins[j0 + (tid - TILE)];
    __syncthreads();

    const float h    = bins[1] - bins[0];
    const float cexp = -0.72134752044f / (h * h);   // -0.5*log2(e)/h^2

    const int sub  = tid & 15;
    const int rrep = tid >> 4;
    const int bi4  = (sub & 3) * 4;
    const int bj4  = (sub >> 2) * 4;

    float acc[16];
#pragma unroll
    for (int q = 0; q < 16; q++) acc[q] = 0.f;

    const int id = (b * NT + ti) * NT + tj;
    const int c  = min(g_cnt[id], CAP);
    const float2* __restrict__ bk = g_bucket + (size_t)id * CAP;

    for (int base = 0; base < c; base += BUF) {
        const int cc = min(BUF, c - base);
        if (tid < cc) {
            const float2 v = bk[base + tid];
            px[tid] = v.x;
            py[tid] = v.y;
        }
        __syncthreads();
        for (int t = tid; t < cc * TILE; t += 256) {
            const int p = t >> 4, k = t & 15;
            const float dx = px[p] - sbx[k];
            const float dy = py[p] - sby[k];
            kxT[p * CPAD + k] = ex2f(cexp * dx * dx);
            kyT[p * CPAD + k] = ex2f(cexp * dy * dy);
        }
        __syncthreads();
        for (int p = rrep; p < cc; p += 16) {
            const float4 kx = *(const float4*)(kxT + p * CPAD + bi4);
            const float4 ky = *(const float4*)(kyT + p * CPAD + bj4);
            acc[ 0] += kx.x * ky.x;  acc[ 1] += kx.x * ky.y;
            acc[ 2] += kx.x * ky.z;  acc[ 3] += kx.x * ky.w;
            acc[ 4] += kx.y * ky.x;  acc[ 5] += kx.y * ky.y;
            acc[ 6] += kx.y * ky.z;  acc[ 7] += kx.y * ky.w;
            acc[ 8] += kx.z * ky.x;  acc[ 9] += kx.z * ky.y;
            acc[10] += kx.z * ky.z;  acc[11] += kx.z * ky.w;
            acc[12] += kx.w * ky.x;  acc[13] += kx.w * ky.y;
            acc[14] += kx.w * ky.z;  acc[15] += kx.w * ky.w;
        }
        __syncthreads();
    }

    // Reduce 16 replicas (fixed order). Reuse kxT (needs 16 KB).
    float* red = kxT;
#pragma unroll
    for (int q = 0; q < 16; q++)
        red[rrep * 256 + sub * 16 + q] = acc[q];
    __syncthreads();

    const int oi   = tid >> 4;
    const int oj   = tid & 15;
    const int sub2 = (oi >> 2) | ((oj >> 2) << 2);
    const int q2   = (oi & 3) * 4 + (oj & 3);
    float v = 0.f;
#pragma unroll
    for (int rr = 0; rr < 16; rr++)
        v += red[rr * 256 + sub2 * 16 + q2];

    g_joint[(b * MDIM + (i0 + oi)) * MDIM + (j0 + oj)] = v;

    // Fused per-batch sum: CTA-reduce v, one atomicAdd per CTA.
    float* sm = kyT;                     // reuse as 256-float scratch
    __syncthreads();
    sm[tid] = v;
    __syncthreads();
    for (int off = 128; off > 0; off >>= 1) {
        if (tid < off) sm[tid] += sm[tid + off];
        __syncthreads();
    }
    if (tid == 0) atomicAdd(&g_sum[b], sm[0]);
}

// ---------------------------------------------------------------------------
__global__ void norm_kernel(float* __restrict__ out, int n4)
{
    const int t = blockIdx.x * 256 + threadIdx.x;
    if (t >= n4) return;
    const int b = (t * 4) / (MDIM * MDIM);
    const float inv = 1.0f / (g_sum[b] + 1e-10f);
    float4 v = ((const float4*)g_joint)[t];
    v.x *= inv; v.y *= inv; v.z *= inv; v.w *= inv;
    ((float4*)out)[t] = v;
}

// ---------------------------------------------------------------------------
extern "C" void kernel_launch(void* const* d_in, const int* in_sizes, int n_in,
                              void* d_out, int out_size)
{
    const float* x    = (const float*)d_in[0];   // (B, N) f32
    const float* y    = (const float*)d_in[1];   // (B, N) f32
    const float* bins = (const float*)d_in[2];   // (M,)  f32

    const int N = in_sizes[0] / NBATCH;

    zero_kernel<<<1, 1024>>>();

    dim3 bgrid((N + 255) / 256, NBATCH);
    bin_kernel<<<bgrid, 256>>>(x, y, bins, N);

    dim3 tgrid(NT, NT, NBATCH);
    tile_kernel<<<tgrid, 256>>>(bins);

    const int n4 = out_size / 4;
    norm_kernel<<<(n4 + 255) / 256, 256>>>((float*)d_out, n4);
}

// round 11
// speedup vs baseline: 1.6085x; 1.0141x over previous
#include <cuda_runtime.h>
#include <cuda_bf16.h>

// ---------------------------------------------------------------------------
// B=4 batches, M=256 bins, N = in_sizes[0]/B particles.
// joint[b,i,j] = sum_n exp(-0.5((x-bins[i])/h)^2) * exp(-0.5((y-bins[j])/h)^2)
// out = joint / (sum_ij joint + 1e-10), h = bins[1]-bins[0].
//
// exp term is EXACTLY 0 in fp32 once |d|/h > 14.4 (below denormal floor) ->
// banded structure. Particles are pre-binned into per-tile buckets (window
// cut 14.6h; 0.2h slack >> fp rounding -> zero-dropping is exact).
// Load balance: each bucket is processed by S=8 split CTAs writing partial
// tiles; a fixed-order reduction sums the splits (deterministic).
// ---------------------------------------------------------------------------

#define NBATCH 4
#define MDIM   256
#define TILE   16
#define NT     16      // tiles per axis
#define SPLIT  8       // split CTAs per bucket
#define CAP    10240   // bucket capacity (max expected ~7.9k central tile)
#define BUF    256     // particles staged per chunk
#define CPAD   20      // 16 table entries + 4 pad floats

// Static scratch (load-time allocation; no runtime alloc).
__device__ float2 g_bucket[NBATCH * NT * NT * CAP];            // ~84 MB
__device__ int    g_cnt[NBATCH * NT * NT];
__device__ float  g_part[NBATCH * SPLIT * MDIM * MDIM];        // 8 MB partials
__device__ float  g_joint[NBATCH * MDIM * MDIM];
__device__ float  g_sum[NBATCH];

__device__ __forceinline__ float ex2f(float a) {
    float r;
    asm("ex2.approx.ftz.f32 %0, %1;" : "=f"(r) : "f"(a));
    return r;
}

// ---------------------------------------------------------------------------
__global__ void zero_kernel()
{
    const int t = threadIdx.x;           // 1024 threads
    g_cnt[t] = 0;
    if (t < NBATCH) g_sum[t] = 0.f;
}

// ---------------------------------------------------------------------------
// One thread per particle: scatter (x,y) into every tile bucket whose window
// contains it (<=3x3). Tile i window (bin units t=(x-b0)/h):
//   i in [ceil((t-29.6)/16), floor((t+14.6)/16)].
__global__ void bin_kernel(const float* __restrict__ x,
                           const float* __restrict__ y,
                           const float* __restrict__ bins, int N)
{
    const int idx = blockIdx.x * 256 + threadIdx.x;
    const int b   = blockIdx.y;
    if (idx >= N) return;

    const float b0   = __ldg(bins);
    const float h    = __ldg(bins + 1) - b0;
    const float invh = 1.0f / h;

    const float xv = __ldg(x + b * N + idx);
    const float yv = __ldg(y + b * N + idx);
    const float tx = (xv - b0) * invh;
    const float ty = (yv - b0) * invh;

    const float s = 1.0f / 16.0f;
    const int ix0 = max(0,      (int)ceilf ((tx - 29.6f) * s));
    const int ix1 = min(NT - 1, (int)floorf((tx + 14.6f) * s));
    const int iy0 = max(0,      (int)ceilf ((ty - 29.6f) * s));
    const int iy1 = min(NT - 1, (int)floorf((ty + 14.6f) * s));

    const float2 v = make_float2(xv, yv);
    for (int i = ix0; i <= ix1; i++)
        for (int j = iy0; j <= iy1; j++) {
            const int id  = (b * NT + i) * NT + j;
            const int pos = atomicAdd(&g_cnt[id], 1);
            if (pos < CAP) g_bucket[id * CAP + pos] = v;
        }
}

// ---------------------------------------------------------------------------
// CTA (ti, tj, b*SPLIT+s) processes slice s of bucket (b,ti,tj) and writes a
// 16x16 partial tile. Per 256-particle chunk: stage -> kx/ky tables (1 MUFU
// per value) -> 16-replica x (4x4 per-thread) outer-product accumulation.
__global__ void __launch_bounds__(256, 4)
tile_kernel(const float* __restrict__ bins)
{
    __shared__ float sbx[TILE], sby[TILE];
    __shared__ float px[BUF], py[BUF];
    __shared__ float kxT[BUF * CPAD];
    __shared__ float kyT[BUF * CPAD];

    const int tid = threadIdx.x;
    const int ti  = blockIdx.x;
    const int tj  = blockIdx.y;
    const int b   = blockIdx.z >> 3;     // z = b*SPLIT + s
    const int s   = blockIdx.z & (SPLIT - 1);
    const int i0  = ti * TILE;
    const int j0  = tj * TILE;

    if (tid < TILE)            sbx[tid]        = bins[i0 + tid];
    else if (tid < 2 * TILE)   sby[tid - TILE] = bins[j0 + (tid - TILE)];
    __syncthreads();

    const float h    = bins[1] - bins[0];
    const float cexp = -0.72134752044f / (h * h);   // -0.5*log2(e)/h^2

    const int sub  = tid & 15;
    const int rrep = tid >> 4;
    const int bi4  = (sub & 3) * 4;
    const int bj4  = (sub >> 2) * 4;

    float acc[16];
#pragma unroll
    for (int q = 0; q < 16; q++) acc[q] = 0.f;

    const int id  = (b * NT + ti) * NT + tj;
    const int c   = min(g_cnt[id], CAP);
    const int len = (c + SPLIT - 1) / SPLIT;
    const int lo  = s * len;
    const int hi  = min(c, lo + len);
    const float2* __restrict__ bk = g_bucket + (size_t)id * CAP;

    for (int base = lo; base < hi; base += BUF) {
        const int cc = min(BUF, hi - base);
        if (tid < cc) {
            const float2 v = bk[base + tid];
            px[tid] = v.x;
            py[tid] = v.y;
        }
        __syncthreads();
        for (int t = tid; t < cc * TILE; t += 256) {
            const int p = t >> 4, k = t & 15;
            const float dx = px[p] - sbx[k];
            const float dy = py[p] - sby[k];
            kxT[p * CPAD + k] = ex2f(cexp * dx * dx);
            kyT[p * CPAD + k] = ex2f(cexp * dy * dy);
        }
        __syncthreads();
        for (int p = rrep; p < cc; p += 16) {
            const float4 kx = *(const float4*)(kxT + p * CPAD + bi4);
            const float4 ky = *(const float4*)(kyT + p * CPAD + bj4);
            acc[ 0] += kx.x * ky.x;  acc[ 1] += kx.x * ky.y;
            acc[ 2] += kx.x * ky.z;  acc[ 3] += kx.x * ky.w;
            acc[ 4] += kx.y * ky.x;  acc[ 5] += kx.y * ky.y;
            acc[ 6] += kx.y * ky.z;  acc[ 7] += kx.y * ky.w;
            acc[ 8] += kx.z * ky.x;  acc[ 9] += kx.z * ky.y;
            acc[10] += kx.z * ky.z;  acc[11] += kx.z * ky.w;
            acc[12] += kx.w * ky.x;  acc[13] += kx.w * ky.y;
            acc[14] += kx.w * ky.z;  acc[15] += kx.w * ky.w;
        }
        __syncthreads();
    }

    // Reduce 16 replicas (fixed order). Reuse kxT (16 KB needed).
    float* red = kxT;
#pragma unroll
    for (int q = 0; q < 16; q++)
        red[rrep * 256 + sub * 16 + q] = acc[q];
    __syncthreads();

    const int oi   = tid >> 4;
    const int oj   = tid & 15;
    const int sub2 = (oi >> 2) | ((oj >> 2) << 2);
    const int q2   = (oi & 3) * 4 + (oj & 3);
    float v = 0.f;
#pragma unroll
    for (int rr = 0; rr < 16; rr++)
        v += red[rr * 256 + sub2 * 16 + q2];

    g_part[((b * SPLIT + s) * MDIM + (i0 + oi)) * MDIM + (j0 + oj)] = v;
}

// ---------------------------------------------------------------------------
// Sum SPLIT partials per element (fixed order -> deterministic), write joint,
// and fold in the per-batch total (block reduce + one atomicAdd per CTA).
// 256 CTAs x 256 threads, one float4 per thread; blocks never straddle a
// batch (1024 elems/block divides 65536 elems/batch).
__global__ void reduce_kernel()
{
    const int t  = blockIdx.x * 256 + threadIdx.x;   // float4 index
    const int b  = (t * 4) / (MDIM * MDIM);
    const int ij = t - b * (MDIM * MDIM / 4);        // float4 index in batch

    float4 v = make_float4(0.f, 0.f, 0.f, 0.f);
#pragma unroll
    for (int s = 0; s < SPLIT; s++) {
        const float4 p = ((const float4*)g_part)[(b * SPLIT + s) *
                                                 (MDIM * MDIM / 4) + ij];
        v.x += p.x; v.y += p.y; v.z += p.z; v.w += p.w;
    }
    ((float4*)g_joint)[t] = v;

    __shared__ float sm[256];
    sm[threadIdx.x] = (v.x + v.y) + (v.z + v.w);
    __syncthreads();
    for (int off = 128; off > 0; off >>= 1) {
        if (threadIdx.x < off) sm[threadIdx.x] += sm[threadIdx.x + off];
        __syncthreads();
    }
    if (threadIdx.x == 0) atomicAdd(&g_sum[b], sm[0]);
}

// ---------------------------------------------------------------------------
__global__ void norm_kernel(float* __restrict__ out, int n4)
{
    const int t = blockIdx.x * 256 + threadIdx.x;
    if (t >= n4) return;
    const int b = (t * 4) / (MDIM * MDIM);
    const float inv = 1.0f / (g_sum[b] + 1e-10f);
    float4 v = ((const float4*)g_joint)[t];
    v.x *= inv; v.y *= inv; v.z *= inv; v.w *= inv;
    ((float4*)out)[t] = v;
}

// ---------------------------------------------------------------------------
extern "C" void kernel_launch(void* const* d_in, const int* in_sizes, int n_in,
                              void* d_out, int out_size)
{
    const float* x    = (const float*)d_in[0];   // (B, N) f32
    const float* y    = (const float*)d_in[1];   // (B, N) f32
    const float* bins = (const float*)d_in[2];   // (M,)  f32

    const int N = in_sizes[0] / NBATCH;

    zero_kernel<<<1, 1024>>>();

    dim3 bgrid((N + 255) / 256, NBATCH);
    bin_kernel<<<bgrid, 256>>>(x, y, bins, N);

    dim3 tgrid(NT, NT, NBATCH * SPLIT);
    tile_kernel<<<tgrid, 256>>>(bins);

    reduce_kernel<<<NBATCH * MDIM * MDIM / 1024, 256>>>();

    const int n4 = out_size / 4;
    norm_kernel<<<(n4 + 255) / 256, 256>>>((float*)d_out, n4);
}

// round 12
// speedup vs baseline: 2.6369x; 1.6393x over previous
#include <cuda_runtime.h>
#include <cuda_bf16.h>

// ---------------------------------------------------------------------------
// B=4 batches, M=256 bins, N = in_sizes[0]/B particles.
// joint[b,i,j] = sum_n exp(-0.5((x-bins[i])/h)^2) * exp(-0.5((y-bins[j])/h)^2)
// out = joint / (sum_ij joint + 1e-10), h = bins[1]-bins[0].
//
// fp32 Gaussian support: term == 0 once |d|/h > 14.4 -> banded. Particles are
// pre-binned into per-(batch,tile) buckets (cut 14.6h, exact w.r.t. fp32
// underflow). Buckets are 8-way SEGMENTED: a warp scatters into segment
// (warp_id & 7); counters are 128B-strided (own L2 line each) to kill atomic
// serialization. Tile split-CTA s consumes segment s -> balanced + cheap.
// ---------------------------------------------------------------------------

#define NBATCH 4
#define MDIM   256
#define TILE   16
#define NT     16        // tiles per axis
#define SPLIT  8         // segments per bucket == split CTAs per bucket
#define SEGCAP 2048      // per-segment capacity (hot segment ~1k expected)
#define BUF    256       // particles staged per chunk
#define CPAD   20        // 16 table entries + 4 pad floats
#define NBUCK  (NBATCH * NT * NT)

// Static scratch (load-time allocation; no runtime alloc).
__device__ float2 g_bucket[NBUCK * SPLIT * SEGCAP];        // ~134 MB
__device__ int    g_cnt[NBUCK * SPLIT * 32];               // 128B-strided ctrs
__device__ float  g_part[NBATCH * SPLIT * MDIM * MDIM];    // 8 MB partials
__device__ float  g_joint[NBATCH * MDIM * MDIM];
__device__ float  g_sum[NBATCH];

__device__ __forceinline__ float ex2f(float a) {
    float r;
    asm("ex2.approx.ftz.f32 %0, %1;" : "=f"(r) : "f"(a));
    return r;
}

// ---------------------------------------------------------------------------
__global__ void zero_kernel()
{
    const int t = blockIdx.x * 256 + threadIdx.x;   // 32 CTAs x 256 = 8192
    if (t < NBUCK * SPLIT) g_cnt[t * 32] = 0;
    if (t < NBATCH)        g_sum[t] = 0.f;
}

// ---------------------------------------------------------------------------
// One thread per particle: scatter (x,y) into every tile bucket whose window
// contains it (<=3x3 tiles). Tile i window (bin units t=(x-b0)/h):
//   i in [ceil((t-29.6)/16), floor((t+14.6)/16)].
// Segment chosen by warp id -> per-counter contention cut 8x, and each
// counter owns a full 128B line.
__global__ void bin_kernel(const float* __restrict__ x,
                           const float* __restrict__ y,
                           const float* __restrict__ bins, int N)
{
    const int idx = blockIdx.x * 256 + threadIdx.x;
    const int b   = blockIdx.y;
    if (idx >= N) return;

    const float b0   = __ldg(bins);
    const float h    = __ldg(bins + 1) - b0;
    const float invh = 1.0f / h;

    const float xv = __ldg(x + b * N + idx);
    const float yv = __ldg(y + b * N + idx);
    const float tx = (xv - b0) * invh;
    const float ty = (yv - b0) * invh;

    const float s = 1.0f / 16.0f;
    const int ix0 = max(0,      (int)ceilf ((tx - 29.6f) * s));
    const int ix1 = min(NT - 1, (int)floorf((tx + 14.6f) * s));
    const int iy0 = max(0,      (int)ceilf ((ty - 29.6f) * s));
    const int iy1 = min(NT - 1, (int)floorf((ty + 14.6f) * s));

    const int seg = (threadIdx.x >> 5) & (SPLIT - 1);
    const float2 v = make_float2(xv, yv);
    for (int i = ix0; i <= ix1; i++)
        for (int j = iy0; j <= iy1; j++) {
            const int id2 = (((b * NT + i) * NT + j) * SPLIT) + seg;
            const int pos = atomicAdd(&g_cnt[id2 * 32], 1);
            if (pos < SEGCAP) g_bucket[(size_t)id2 * SEGCAP + pos] = v;
        }
}

// ---------------------------------------------------------------------------
// CTA (ti, tj, b*SPLIT+s) processes segment s of bucket (b,ti,tj); writes a
// 16x16 partial tile. Per chunk: stage (reg-double-buffered LDG) -> kx/ky
// tables (1 MUFU/value) -> 16-replica x (4x4/thread) outer-product accum.
__global__ void __launch_bounds__(256, 4)
tile_kernel(const float* __restrict__ bins)
{
    __shared__ float sbx[TILE], sby[TILE];
    __shared__ float px[BUF], py[BUF];
    __shared__ float kxT[BUF * CPAD];
    __shared__ float kyT[BUF * CPAD];

    const int tid = threadIdx.x;
    const int ti  = blockIdx.x;
    const int tj  = blockIdx.y;
    const int b   = blockIdx.z >> 3;     // z = b*SPLIT + s
    const int s   = blockIdx.z & (SPLIT - 1);
    const int i0  = ti * TILE;
    const int j0  = tj * TILE;

    if (tid < TILE)            sbx[tid]        = bins[i0 + tid];
    else if (tid < 2 * TILE)   sby[tid - TILE] = bins[j0 + (tid - TILE)];
    __syncthreads();

    const float h    = bins[1] - bins[0];
    const float cexp = -0.72134752044f / (h * h);   // -0.5*log2(e)/h^2

    const int sub  = tid & 15;
    const int rrep = tid >> 4;
    const int bi4  = (sub & 3) * 4;
    const int bj4  = (sub >> 2) * 4;

    float acc[16];
#pragma unroll
    for (int q = 0; q < 16; q++) acc[q] = 0.f;

    const int id2 = (((b * NT + ti) * NT + tj) * SPLIT) + s;
    const int c   = min(g_cnt[id2 * 32], SEGCAP);
    const float2* __restrict__ bk = g_bucket + (size_t)id2 * SEGCAP;

    // Register prefetch of chunk 0.
    float2 nv = make_float2(0.f, 0.f);
    if (tid < c) nv = __ldg(bk + tid);

    for (int base = 0; base < c; base += BUF) {
        const int cc = min(BUF, c - base);
        if (tid < cc) { px[tid] = nv.x; py[tid] = nv.y; }

        // Issue next chunk's load NOW; it overlaps table+FMA below.
        const int nb = base + BUF;
        if (nb + tid < c) nv = __ldg(bk + nb + tid);

        __syncthreads();
        for (int t = tid; t < cc * TILE; t += 256) {
            const int p = t >> 4, k = t & 15;
            const float dx = px[p] - sbx[k];
            const float dy = py[p] - sby[k];
            kxT[p * CPAD + k] = ex2f(cexp * dx * dx);
            kyT[p * CPAD + k] = ex2f(cexp * dy * dy);
        }
        __syncthreads();
        for (int p = rrep; p < cc; p += 16) {
            const float4 kx = *(const float4*)(kxT + p * CPAD + bi4);
            const float4 ky = *(const float4*)(kyT + p * CPAD + bj4);
            acc[ 0] += kx.x * ky.x;  acc[ 1] += kx.x * ky.y;
            acc[ 2] += kx.x * ky.z;  acc[ 3] += kx.x * ky.w;
            acc[ 4] += kx.y * ky.x;  acc[ 5] += kx.y * ky.y;
            acc[ 6] += kx.y * ky.z;  acc[ 7] += kx.y * ky.w;
            acc[ 8] += kx.z * ky.x;  acc[ 9] += kx.z * ky.y;
            acc[10] += kx.z * ky.z;  acc[11] += kx.z * ky.w;
            acc[12] += kx.w * ky.x;  acc[13] += kx.w * ky.y;
            acc[14] += kx.w * ky.z;  acc[15] += kx.w * ky.w;
        }
        __syncthreads();
    }

    // Reduce 16 replicas (fixed order). Reuse kxT (16 KB needed).
    float* red = kxT;
#pragma unroll
    for (int q = 0; q < 16; q++)
        red[rrep * 256 + sub * 16 + q] = acc[q];
    __syncthreads();

    const int oi   = tid >> 4;
    const int oj   = tid & 15;
    const int sub2 = (oi >> 2) | ((oj >> 2) << 2);
    const int q2   = (oi & 3) * 4 + (oj & 3);
    float v = 0.f;
#pragma unroll
    for (int rr = 0; rr < 16; rr++)
        v += red[rr * 256 + sub2 * 16 + q2];

    g_part[((b * SPLIT + s) * MDIM + (i0 + oi)) * MDIM + (j0 + oj)] = v;
}

// ---------------------------------------------------------------------------
// Sum SPLIT partials per element (fixed order -> deterministic), write joint,
// fold in per-batch total (block reduce + one atomicAdd per CTA). Blocks
// never straddle a batch (1024 elems/block | 65536 elems/batch).
__global__ void reduce_kernel()
{
    const int t  = blockIdx.x * 256 + threadIdx.x;   // float4 index
    const int b  = (t * 4) / (MDIM * MDIM);
    const int ij = t - b * (MDIM * MDIM / 4);

    float4 v = make_float4(0.f, 0.f, 0.f, 0.f);
#pragma unroll
    for (int s = 0; s < SPLIT; s++) {
        const float4 p = ((const float4*)g_part)[(b * SPLIT + s) *
                                                 (MDIM * MDIM / 4) + ij];
        v.x += p.x; v.y += p.y; v.z += p.z; v.w += p.w;
    }
    ((float4*)g_joint)[t] = v;

    __shared__ float sm[256];
    sm[threadIdx.x] = (v.x + v.y) + (v.z + v.w);
    __syncthreads();
    for (int off = 128; off > 0; off >>= 1) {
        if (threadIdx.x < off) sm[threadIdx.x] += sm[threadIdx.x + off];
        __syncthreads();
    }
    if (threadIdx.x == 0) atomicAdd(&g_sum[b], sm[0]);
}

// ---------------------------------------------------------------------------
__global__ void norm_kernel(float* __restrict__ out, int n4)
{
    const int t = blockIdx.x * 256 + threadIdx.x;
    if (t >= n4) return;
    const int b = (t * 4) / (MDIM * MDIM);
    const float inv = 1.0f / (g_sum[b] + 1e-10f);
    float4 v = ((const float4*)g_joint)[t];
    v.x *= inv; v.y *= inv; v.z *= inv; v.w *= inv;
    ((float4*)out)[t] = v;
}

// ---------------------------------------------------------------------------
extern "C" void kernel_launch(void* const* d_in, const int* in_sizes, int n_in,
                              void* d_out, int out_size)
{
    const float* x    = (const float*)d_in[0];   // (B, N) f32
    const float* y    = (const float*)d_in[1];   // (B, N) f32
    const float* bins = (const float*)d_in[2];   // (M,)  f32

    const int N = in_sizes[0] / NBATCH;

    zero_kernel<<<(NBUCK * SPLIT + 255) / 256, 256>>>();

    dim3 bgrid((N + 255) / 256, NBATCH);
    bin_kernel<<<bgrid, 256>>>(x, y, bins, N);

    dim3 tgrid(NT, NT, NBATCH * SPLIT);
    tile_kernel<<<tgrid, 256>>>(bins);

    reduce_kernel<<<NBATCH * MDIM * MDIM / 1024, 256>>>();

    const int n4 = out_size / 4;
    norm_kernel<<<(n4 + 255) / 256, 256>>>((float*)d_out, n4);
}

// round 14
// speedup vs baseline: 2.7388x; 1.0386x over previous
#include <cuda_runtime.h>
#include <cuda_bf16.h>

// ---------------------------------------------------------------------------
// B=4 batches, M=256 bins, N = in_sizes[0]/B particles.
// joint[b,i,j] = sum_n exp(-0.5((x-bins[i])/h)^2) * exp(-0.5((y-bins[j])/h)^2)
// out = joint / (sum_ij joint + 1e-10), h = bins[1]-bins[0].
//
// fp32 Gaussian support: term == 0 once |d|/h > 14.4 -> banded. Particles are
// pre-binned into per-(batch,tile) buckets (cut 14.6h, exact w.r.t. fp32
// underflow). Buckets are 8-way SEGMENTED (warp-id segment, 128B-strided
// counters -> no L2 atomic serialization). Tile CTA s consumes segment s.
// reduce+norm fused via arrival counter (256 co-resident CTAs).
// ---------------------------------------------------------------------------

#define NBATCH 4
#define MDIM   256
#define TILE   16
#define NT     16        // tiles per axis
#define SPLIT  8         // segments per bucket == split CTAs per bucket
#define SEGCAP 2048      // per-segment capacity (hot segment ~1k expected)
#define BUF    256       // particles per chunk
#define CPAD   20        // 16 table entries + 4 pad floats
#define NBUCK  (NBATCH * NT * NT)

// Static scratch (load-time allocation; no runtime alloc).
__device__ float2 g_bucket[NBUCK * SPLIT * SEGCAP];        // ~134 MB
__device__ int    g_cnt[NBUCK * SPLIT * 32];               // 128B-strided ctrs
__device__ float  g_part[NBATCH * SPLIT * MDIM * MDIM];    // 8 MB partials
__device__ float  g_sum[NBATCH];
__device__ int    g_done;

__device__ __forceinline__ float ex2f(float a) {
    float r;
    asm("ex2.approx.ftz.f32 %0, %1;" : "=f"(r) : "f"(a));
    return r;
}

// ---------------------------------------------------------------------------
__global__ void zero_kernel()
{
    const int t = blockIdx.x * 256 + threadIdx.x;
    if (t < NBUCK * SPLIT) g_cnt[t * 32] = 0;
    if (t < NBATCH)        g_sum[t] = 0.f;
    if (t == NBATCH)       g_done = 0;
}

// ---------------------------------------------------------------------------
// One thread per particle: scatter (x,y) into every tile bucket whose window
// contains it (<=3x3 tiles). Tile i window (bin units t=(x-b0)/h):
//   i in [ceil((t-29.6)/16), floor((t+14.6)/16)].
__global__ void bin_kernel(const float* __restrict__ x,
                           const float* __restrict__ y,
                           const float* __restrict__ bins, int N)
{
    const int idx = blockIdx.x * 256 + threadIdx.x;
    const int b   = blockIdx.y;
    if (idx >= N) return;

    const float b0   = __ldg(bins);
    const float h    = __ldg(bins + 1) - b0;
    const float invh = 1.0f / h;

    const float xv = __ldg(x + b * N + idx);
    const float yv = __ldg(y + b * N + idx);
    const float tx = (xv - b0) * invh;
    const float ty = (yv - b0) * invh;

    const float s = 1.0f / 16.0f;
    const int ix0 = max(0,      (int)ceilf ((tx - 29.6f) * s));
    const int ix1 = min(NT - 1, (int)floorf((tx + 14.6f) * s));
    const int iy0 = max(0,      (int)ceilf ((ty - 29.6f) * s));
    const int iy1 = min(NT - 1, (int)floorf((ty + 14.6f) * s));

    const int seg = (threadIdx.x >> 5) & (SPLIT - 1);
    const float2 v = make_float2(xv, yv);
    for (int i = ix0; i <= ix1; i++)
        for (int j = iy0; j <= iy1; j++) {
            const int id2 = (((b * NT + i) * NT + j) * SPLIT) + seg;
            const int pos = atomicAdd(&g_cnt[id2 * 32], 1);
            if (pos < SEGCAP) g_bucket[(size_t)id2 * SEGCAP + pos] = v;
        }
}

// ---------------------------------------------------------------------------
// CTA (ti, tj, b*SPLIT+s) processes segment s of bucket (b,ti,tj); writes a
// 16x16 partial tile. Per chunk (2 barriers): each thread computes its OWN
// particle's 16+16 table entries from the prefetched register (float4 STS,
// conflict-free phases) -> 16-replica x (4x4/thread) outer-product accum.
__global__ void __launch_bounds__(256, 4)
tile_kernel(const float* __restrict__ bins)
{
    __shared__ float sbx[TILE], sby[TILE];
    __shared__ float kxT[BUF * CPAD];
    __shared__ float kyT[BUF * CPAD];

    const int tid = threadIdx.x;
    const int ti  = blockIdx.x;
    const int tj  = blockIdx.y;
    const int b   = blockIdx.z >> 3;     // z = b*SPLIT + s
    const int s   = blockIdx.z & (SPLIT - 1);
    const int i0  = ti * TILE;
    const int j0  = tj * TILE;

    if (tid < TILE)            sbx[tid]        = bins[i0 + tid];
    else if (tid < 2 * TILE)   sby[tid - TILE] = bins[j0 + (tid - TILE)];
    __syncthreads();

    const float h    = bins[1] - bins[0];
    const float cexp = -0.72134752044f / (h * h);   // -0.5*log2(e)/h^2

    const int sub  = tid & 15;
    const int rrep = tid >> 4;
    const int bi4  = (sub & 3) * 4;
    const int bj4  = (sub >> 2) * 4;

    float acc[16];
#pragma unroll
    for (int q = 0; q < 16; q++) acc[q] = 0.f;

    const int id2 = (((b * NT + ti) * NT + tj) * SPLIT) + s;
    const int c   = min(g_cnt[id2 * 32], SEGCAP);
    const float2* __restrict__ bk = g_bucket + (size_t)id2 * SEGCAP;

    // Register prefetch of this thread's chunk-0 particle.
    float2 nv = make_float2(0.f, 0.f);
    if (tid < c) nv = __ldg(bk + tid);

    for (int base = 0; base < c; base += BUF) {
        const int cc = min(BUF, c - base);
        const float2 v = nv;

        // Issue next chunk's load NOW; overlaps table+FMA below.
        const int nb = base + BUF;
        if (nb + tid < c) nv = __ldg(bk + nb + tid);

        if (tid < cc) {
            float* rx = kxT + tid * CPAD;
            float* ry = kyT + tid * CPAD;
#pragma unroll
            for (int k0 = 0; k0 < TILE; k0 += 4) {
                float4 a, e;
                float d;
                d = v.x - sbx[k0 + 0]; a.x = ex2f(cexp * d * d);
                d = v.x - sbx[k0 + 1]; a.y = ex2f(cexp * d * d);
                d = v.x - sbx[k0 + 2]; a.z = ex2f(cexp * d * d);
                d = v.x - sbx[k0 + 3]; a.w = ex2f(cexp * d * d);
                d = v.y - sby[k0 + 0]; e.x = ex2f(cexp * d * d);
                d = v.y - sby[k0 + 1]; e.y = ex2f(cexp * d * d);
                d = v.y - sby[k0 + 2]; e.z = ex2f(cexp * d * d);
                d = v.y - sby[k0 + 3]; e.w = ex2f(cexp * d * d);
                *(float4*)(rx + k0) = a;
                *(float4*)(ry + k0) = e;
            }
        }
        __syncthreads();

        int p = rrep;
        for (; p + 16 < cc; p += 32) {
            const float4 kx0 = *(const float4*)(kxT + p * CPAD + bi4);
            const float4 ky0 = *(const float4*)(kyT + p * CPAD + bj4);
            const float4 kx1 = *(const float4*)(kxT + (p + 16) * CPAD + bi4);
            const float4 ky1 = *(const float4*)(kyT + (p + 16) * CPAD + bj4);
            acc[ 0] += kx0.x * ky0.x;  acc[ 1] += kx0.x * ky0.y;
            acc[ 2] += kx0.x * ky0.z;  acc[ 3] += kx0.x * ky0.w;
            acc[ 4] += kx0.y * ky0.x;  acc[ 5] += kx0.y * ky0.y;
            acc[ 6] += kx0.y * ky0.z;  acc[ 7] += kx0.y * ky0.w;
            acc[ 8] += kx0.z * ky0.x;  acc[ 9] += kx0.z * ky0.y;
            acc[10] += kx0.z * ky0.z;  acc[11] += kx0.z * ky0.w;
            acc[12] += kx0.w * ky0.x;  acc[13] += kx0.w * ky0.y;
            acc[14] += kx0.w * ky0.z;  acc[15] += kx0.w * ky0.w;
            acc[ 0] += kx1.x * ky1.x;  acc[ 1] += kx1.x * ky1.y;
            acc[ 2] += kx1.x * ky1.z;  acc[ 3] += kx1.x * ky1.w;
            acc[ 4] += kx1.y * ky1.x;  acc[ 5] += kx1.y * ky1.y;
            acc[ 6] += kx1.y * ky1.z;  acc[ 7] += kx1.y * ky1.w;
            acc[ 8] += kx1.z * ky1.x;  acc[ 9] += kx1.z * ky1.y;
            acc[10] += kx1.z * ky1.z;  acc[11] += kx1.z * ky1.w;
            acc[12] += kx1.w * ky1.x;  acc[13] += kx1.w * ky1.y;
            acc[14] += kx1.w * ky1.z;  acc[15] += kx1.w * ky1.w;
        }
        if (p < cc) {
            const float4 kx = *(const float4*)(kxT + p * CPAD + bi4);
            const float4 ky = *(const float4*)(kyT + p * CPAD + bj4);
            acc[ 0] += kx.x * ky.x;  acc[ 1] += kx.x * ky.y;
            acc[ 2] += kx.x * ky.z;  acc[ 3] += kx.x * ky.w;
            acc[ 4] += kx.y * ky.x;  acc[ 5] += kx.y * ky.y;
            acc[ 6] += kx.y * ky.z;  acc[ 7] += kx.y * ky.w;
            acc[ 8] += kx.z * ky.x;  acc[ 9] += kx.z * ky.y;
            acc[10] += kx.z * ky.z;  acc[11] += kx.z * ky.w;
            acc[12] += kx.w * ky.x;  acc[13] += kx.w * ky.y;
            acc[14] += kx.w * ky.z;  acc[15] += kx.w * ky.w;
        }
        __syncthreads();
    }

    // Reduce 16 replicas (fixed order). Reuse kxT (16 KB needed).
    float* red = kxT;
#pragma unroll
    for (int q = 0; q < 16; q++)
        red[rrep * 256 + sub * 16 + q] = acc[q];
    __syncthreads();

    const int oi   = tid >> 4;
    const int oj   = tid & 15;
    const int sub2 = (oi >> 2) | ((oj >> 2) << 2);
    const int q2   = (oi & 3) * 4 + (oj & 3);
    float v = 0.f;
#pragma unroll
    for (int rr = 0; rr < 16; rr++)
        v += red[rr * 256 + sub2 * 16 + q2];

    g_part[((b * SPLIT + s) * MDIM + (i0 + oi)) * MDIM + (j0 + oj)] = v;
}

// ---------------------------------------------------------------------------
// Fused reduce + normalize. 256 CTAs x 256 threads (all co-resident; 32 regs
// / 1KB smem -> >=8 CTAs/SM x 148 SMs >> 256, so the spin always terminates).
// Phase 1: sum SPLIT partials per element (fixed order), block-reduce the
// batch total, one atomicAdd per CTA, release via g_done.
// Phase 2: spin on g_done, then normalize the register-resident float4 and
// write d_out directly. Blocks never straddle a batch (1024 | 65536).
__global__ void reduce_norm_kernel(float* __restrict__ out)
{
    const int t  = blockIdx.x * 256 + threadIdx.x;   // float4 index
    const int b  = (t * 4) / (MDIM * MDIM);
    const int ij = t - b * (MDIM * MDIM / 4);

    float4 v = make_float4(0.f, 0.f, 0.f, 0.f);
#pragma unroll
    for (int s = 0; s < SPLIT; s++) {
        const float4 p = ((const float4*)g_part)[(b * SPLIT + s) *
                                                 (MDIM * MDIM / 4) + ij];
        v.x += p.x; v.y += p.y; v.z += p.z; v.w += p.w;
    }

    __shared__ float sm[256];
    sm[threadIdx.x] = (v.x + v.y) + (v.z + v.w);
    __syncthreads();
    for (int off = 128; off > 0; off >>= 1) {
        if (threadIdx.x < off) sm[threadIdx.x] += sm[threadIdx.x + off];
        __syncthreads();
    }
    if (threadIdx.x == 0) {
        atomicAdd(&g_sum[b], sm[0]);
        __threadfence();                       // release g_sum before arrive
        atomicAdd(&g_done, 1);
        while (*(volatile int*)&g_done < (int)gridDim.x) { }
    }
    __syncthreads();

    const float sv  = *(volatile float*)&g_sum[b];
    const float inv = 1.0f / (sv + 1e-10f);
    v.x *= inv; v.y *= inv; v.z *= inv; v.w *= inv;
    ((float4*)out)[t] = v;
}

// ---------------------------------------------------------------------------
extern "C" void kernel_launch(void* const* d_in, const int* in_sizes, int n_in,
                              void* d_out, int out_size)
{
    const float* x    = (const float*)d_in[0];   // (B, N) f32
    const float* y    = (const float*)d_in[1];   // (B, N) f32
    const float* bins = (const float*)d_in[2];   // (M,)  f32

    const int N = in_sizes[0] / NBATCH;

    zero_kernel<<<(NBUCK * SPLIT + 255) / 256, 256>>>();

    dim3 bgrid((N + 255) / 256, NBATCH);
    bin_kernel<<<bgrid, 256>>>(x, y, bins, N);

    dim3 tgrid(NT, NT, NBATCH * SPLIT);
    tile_kernel<<<tgrid, 256>>>(bins);

    reduce_norm_kernel<<<NBATCH * MDIM * MDIM / 1024, 256>>>((float*)d_out);
}